// round 14
// baseline (speedup 1.0000x reference)
#include <cuda_runtime.h>
#include <cstdint>

#define T_ 128
#define V_ 5023
#define K_ 16
#define NTV (T_ * V_)
#define THREADS 512

extern __shared__ float s_rec[];  // [6 * V_] : {can.xyz, def.xyz} per vertex

// dtype-robust active-neighbor bitmask
__device__ __forceinline__ unsigned mask_bits(int mode, const void* __restrict__ maskp, int v) {
    unsigned amask = 0;
    if (mode == 0) {
        uint4 mw = *(const uint4*)((const unsigned char*)maskp + (size_t)v * K_);
        unsigned ws[4] = {mw.x, mw.y, mw.z, mw.w};
#pragma unroll
        for (int i = 0; i < K_; i++)
            if ((ws[i >> 2] >> ((i & 3) * 8)) & 0xFF) amask |= (1u << i);
    } else if (mode == 1) {
        const int4* mi = (const int4*)((const int*)maskp + (size_t)v * K_);
#pragma unroll
        for (int c = 0; c < 4; c++) {
            int4 x = mi[c];
            if (x.x) amask |= 1u << (c * 4 + 0);
            if (x.y) amask |= 1u << (c * 4 + 1);
            if (x.z) amask |= 1u << (c * 4 + 2);
            if (x.w) amask |= 1u << (c * 4 + 3);
        }
    } else {
        const float4* mf = (const float4*)((const float*)maskp + (size_t)v * K_);
#pragma unroll
        for (int c = 0; c < 4; c++) {
            float4 x = mf[c];
            if (x.x != 0.0f) amask |= 1u << (c * 4 + 0);
            if (x.y != 0.0f) amask |= 1u << (c * 4 + 1);
            if (x.z != 0.0f) amask |= 1u << (c * 4 + 2);
            if (x.w != 0.0f) amask |= 1u << (c * 4 + 3);
        }
    }
    return amask;
}

// branchless gather: inactive slot loads zeros => p=-c, q=-d (matches reference)
__device__ __forceinline__ void gather_cov(
    int v, unsigned amask, const int* __restrict__ nbr,
    float& cx, float& cy, float& cz, float& dx, float& dy, float& dz,
    float& A00, float& A01, float& A02,
    float& A10, float& A11, float& A12,
    float& A20, float& A21, float& A22) {
    const float* rv = s_rec + 6 * v;
    cx = rv[0]; cy = rv[1]; cz = rv[2];
    dx = rv[3]; dy = rv[4]; dz = rv[5];
    A00 = A01 = A02 = A10 = A11 = A12 = A20 = A21 = A22 = 0.0f;
    const int4* ni = (const int4*)(nbr + (size_t)v * K_);
#pragma unroll
    for (int c = 0; c < 4; c++) {
        int4 nbc = ni[c];
        unsigned sub = amask >> (c * 4);
#pragma unroll
        for (int kk = 0; kk < 4; kk++) {
            int j = (kk == 0) ? nbc.x : (kk == 1) ? nbc.y : (kk == 2) ? nbc.z : nbc.w;
            bool act = (sub >> kk) & 1u;
            float2 r0 = make_float2(0.f, 0.f);
            float2 r1 = make_float2(0.f, 0.f);
            float2 r2 = make_float2(0.f, 0.f);
            if (act) {
                const float2* rj = (const float2*)(s_rec + 6 * j);
                r0 = rj[0]; r1 = rj[1]; r2 = rj[2];
            }
            float px = r0.x - cx, py = r0.y - cy, pz = r1.x - cz;
            float qx = r1.y - dx, qy = r2.x - dy, qz = r2.y - dz;
            A00 = fmaf(qx, px, A00); A01 = fmaf(qx, py, A01); A02 = fmaf(qx, pz, A02);
            A10 = fmaf(qy, px, A10); A11 = fmaf(qy, py, A11); A12 = fmaf(qy, pz, A12);
            A20 = fmaf(qz, px, A20); A21 = fmaf(qz, py, A21); A22 = fmaf(qz, pz, A22);
        }
    }
}

// rotation: optimal quaternion from cross-covariance A (A[i][j] = sum q_i p_j)
__device__ __forceinline__ float4 rot_quat(
    float A00, float A01, float A02,
    float A10, float A11, float A12,
    float A20, float A21, float A22) {
    float k00 = A00 + A11 + A22;
    float k11 = A00 - A11 - A22;
    float k22 = -A00 + A11 - A22;
    float k33 = -A00 - A11 + A22;
    float k01 = A21 - A12;
    float k02 = A02 - A20;
    float k03 = A10 - A01;
    float k12 = A01 + A10;
    float k13 = A02 + A20;
    float k23 = A12 + A21;

    float trAtA = A00 * A00 + A01 * A01 + A02 * A02 +
                  A10 * A10 + A11 * A11 + A12 * A12 +
                  A20 * A20 + A21 * A21 + A22 * A22;
    float c2 = -2.0f * trAtA;
    float detA = A00 * (A11 * A22 - A12 * A21)
               - A01 * (A10 * A22 - A12 * A20)
               + A02 * (A10 * A21 - A11 * A20);
    float c1 = -8.0f * detA;
    float M0 = k11 * (k22 * k33 - k23 * k23)
             - k12 * (k12 * k33 - k23 * k13)
             + k13 * (k12 * k23 - k22 * k13);
    float M1 = k01 * (k22 * k33 - k23 * k23)
             - k12 * (k02 * k33 - k23 * k03)
             + k13 * (k02 * k23 - k22 * k03);
    float M2 = k01 * (k12 * k33 - k23 * k13)
             - k11 * (k02 * k33 - k23 * k03)
             + k13 * (k02 * k13 - k12 * k03);
    float M3 = k01 * (k12 * k23 - k22 * k13)
             - k11 * (k02 * k23 - k22 * k03)
             + k12 * (k02 * k13 - k12 * k03);
    float c0 = k00 * M0 - k01 * M1 + k02 * M2 - k03 * M3;

    float lam = 1.7320508f * sqrtf(trAtA);
    float fp2 = 1.0f;
#pragma unroll
    for (int it = 0; it < 8; it++) {
        float lam2 = lam * lam;
        float f = (lam2 + c2) * lam2 + fmaf(c1, lam, c0);
        fp2 = fmaf(4.0f * lam2 + 2.0f * c2, lam, c1);
        lam -= __fdividef(f, fp2);
    }

    float b00 = k00 - lam, b11 = k11 - lam, b22 = k22 - lam, b33 = k33 - lam;
    float a3 = 4.0f * lam;
    float a2 = fmaf(6.0f * lam, lam, c2);
    float a1 = fp2;

    float u10 = b00, u11 = k01, u12 = k02, u13 = k03;
    float u20 = b00 * u10 + k01 * u11 + k02 * u12 + k03 * u13;
    float u21 = k01 * u10 + b11 * u11 + k12 * u12 + k13 * u13;
    float u22 = k02 * u10 + k12 * u11 + b22 * u12 + k23 * u13;
    float u23 = k03 * u10 + k13 * u11 + k23 * u12 + b33 * u13;
    float u30 = b00 * u20 + k01 * u21 + k02 * u22 + k03 * u23;
    float u31 = k01 * u20 + b11 * u21 + k12 * u22 + k13 * u23;
    float u32 = k02 * u20 + k12 * u21 + b22 * u22 + k23 * u23;
    float u33 = k03 * u20 + k13 * u21 + k23 * u22 + b33 * u23;

    float qw = u30 + a3 * u20 + a2 * u10 + a1;
    float qx = u31 + a3 * u21 + a2 * u11;
    float qy = u32 + a3 * u22 + a2 * u12;
    float qz = u33 + a3 * u23 + a2 * u13;

    float nq = fmaf(qw, qw, fmaf(qx, qx, fmaf(qy, qy, qz * qz)));
    if (nq < 1e-4f * a1 * a1) {
        // rare fallback (near-180-degree rotation): full adjugate, best column
        float C00 = b00 * b00 + k01 * k01 + k02 * k02 + k03 * k03;
        float C01 = b00 * k01 + k01 * b11 + k02 * k12 + k03 * k13;
        float C02 = b00 * k02 + k01 * k12 + k02 * b22 + k03 * k23;
        float C03 = b00 * k03 + k01 * k13 + k02 * k23 + k03 * b33;
        float C11 = k01 * k01 + b11 * b11 + k12 * k12 + k13 * k13;
        float C12 = k01 * k02 + b11 * k12 + k12 * b22 + k13 * k23;
        float C13 = k01 * k03 + b11 * k13 + k12 * k23 + k13 * b33;
        float C22 = k02 * k02 + k12 * k12 + b22 * b22 + k23 * k23;
        float C23 = k02 * k03 + k12 * k13 + b22 * k23 + k23 * b33;
        float C33 = k03 * k03 + k13 * k13 + k23 * k23 + b33 * b33;
        float P01v = b00 * C01 + k01 * C11 + k02 * C12 + k03 * C13;
        float P02v = b00 * C02 + k01 * C12 + k02 * C22 + k03 * C23;
        float P03v = b00 * C03 + k01 * C13 + k02 * C23 + k03 * C33;
        float P11v = k01 * C01 + b11 * C11 + k12 * C12 + k13 * C13;
        float P12v = k01 * C02 + b11 * C12 + k12 * C22 + k13 * C23;
        float P13v = k01 * C03 + b11 * C13 + k12 * C23 + k13 * C33;
        float P22v = k02 * C02 + k12 * C12 + b22 * C22 + k23 * C23;
        float P23v = k02 * C03 + k12 * C13 + b22 * C23 + k23 * C33;
        float P33v = k03 * C03 + k13 * C13 + k23 * C23 + b33 * C33;
        float N01 = P01v + a3 * C01 + a2 * k01;
        float N02 = P02v + a3 * C02 + a2 * k02;
        float N03 = P03v + a3 * C03 + a2 * k03;
        float N11 = P11v + a3 * C11 + a2 * b11 + a1;
        float N12 = P12v + a3 * C12 + a2 * k12;
        float N13 = P13v + a3 * C13 + a2 * k13;
        float N22 = P22v + a3 * C22 + a2 * b22 + a1;
        float N23 = P23v + a3 * C23 + a2 * k23;
        float N33 = P33v + a3 * C33 + a2 * b33 + a1;
        float bd = nq > 0 ? sqrtf(nq) : 0.0f;
        if (fabsf(N11) > bd) { bd = fabsf(N11); qw = N01; qx = N11; qy = N12; qz = N13; }
        if (fabsf(N22) > bd) { bd = fabsf(N22); qw = N02; qx = N12; qy = N22; qz = N23; }
        if (fabsf(N33) > bd) { qw = N03; qx = N13; qy = N23; qz = N33; }
    }

    // sign convention: component with largest |value| (w,x,y,z, first on ties) positive
    float aw = fabsf(qw), ax = fabsf(qx), ay = fabsf(qy), az = fabsf(qz);
    float besta = aw, piv = qw;
    if (ax > besta) { besta = ax; piv = qx; }
    if (ay > besta) { besta = ay; piv = qy; }
    if (az > besta) { besta = az; piv = qz; }
    float invn = rsqrtf(fmaf(qw, qw, fmaf(qx, qx, fmaf(qy, qy, qz * qz))));
    if (piv < 0.0f) invn = -invn;

    return make_float4(qw * invn, qx * invn, qy * invn, qz * invn);
}

__global__ void __launch_bounds__(THREADS)
se3_frame_kernel(const float* __restrict__ can, const float* __restrict__ def,
                 const int* __restrict__ nbr, const void* __restrict__ maskp,
                 float* __restrict__ out) {
    const int t = blockIdx.x;
    const int tid = threadIdx.x;
    const float* canT = can + (size_t)t * (V_ * 3);
    const float* defT = def + (size_t)t * (V_ * 3);

    __shared__ int s_mode;  // 0 = uint8 bool, 1 = int32, 2 = float32

    if (tid < 32) {
        unsigned int x = ((const unsigned int*)maskp)[tid];
        bool weird = (x != 0u) && (x != 1u) && (x != 0x3F800000u);
        bool isf32 = (x == 0x3F800000u);
        unsigned bp = __ballot_sync(0xffffffffu, weird);
        unsigned fp = __ballot_sync(0xffffffffu, isf32);
        if (tid == 0) s_mode = bp ? 0 : (fp ? 2 : 1);
    }

    // stage this frame's positions into smem as packed 24B records
    for (int v = tid; v < V_; v += THREADS) {
        int b = 3 * v;
        float* r = s_rec + 6 * v;
        r[0] = canT[b]; r[1] = canT[b + 1]; r[2] = canT[b + 2];
        r[3] = defT[b]; r[4] = defT[b + 1]; r[5] = defT[b + 2];
    }
    __syncthreads();

    const int mode = s_mode;
    float* outt = out + (size_t)NTV * 4;

    // 2 vertices per thread per iteration: vA = v0, vB = v0 + THREADS.
    // V_=5023, step 1024: exactly 5 uniform iterations for every thread.
#pragma unroll 1
    for (int v0 = tid; v0 < V_; v0 += 2 * THREADS) {
        int vA = v0;
        int vB = v0 + THREADS;
        bool hasB = (vB < V_);
        int vBs = hasB ? vB : vA;  // safe index for speculative work

        unsigned mA = mask_bits(mode, maskp, vA);
        unsigned mB = mask_bits(mode, maskp, vBs);

        float cxA, cyA, czA, dxA, dyA, dzA;
        float a00, a01, a02, a10, a11, a12, a20, a21, a22;
        float cxB, cyB, czB, dxB, dyB, dzB;
        float e00, e01, e02, e10, e11, e12, e20, e21, e22;

        gather_cov(vA, mA, nbr, cxA, cyA, czA, dxA, dyA, dzA,
                   a00, a01, a02, a10, a11, a12, a20, a21, a22);
        gather_cov(vBs, mB, nbr, cxB, cyB, czB, dxB, dyB, dzB,
                   e00, e01, e02, e10, e11, e12, e20, e21, e22);

        int idxA = t * V_ + vA;
        int idxB = t * V_ + vBs;

        // translations
        outt[idxA * 3 + 0] = dxA - cxA;
        outt[idxA * 3 + 1] = dyA - cyA;
        outt[idxA * 3 + 2] = dzA - czA;
        if (hasB) {
            outt[idxB * 3 + 0] = dxB - cxB;
            outt[idxB * 3 + 1] = dyB - cyB;
            outt[idxB * 3 + 2] = dzB - czB;
        }

        // two independent rotation chains — interleaved by the scheduler
        float4 qA = rot_quat(a00, a01, a02, a10, a11, a12, a20, a21, a22);
        float4 qB = rot_quat(e00, e01, e02, e10, e11, e12, e20, e21, e22);

        ((float4*)out)[idxA] = qA;
        if (hasB) ((float4*)out)[idxB] = qB;
    }
}

extern "C" void kernel_launch(void* const* d_in, const int* in_sizes, int n_in,
                              void* d_out, int out_size) {
    const float* can = (const float*)d_in[0];
    const float* def = (const float*)d_in[1];
    const int* nbr = (const int*)d_in[2];
    const void* mask = d_in[3];
    float* out = (float*)d_out;

    static int smem_set = 0;
    const int smem_bytes = 6 * V_ * (int)sizeof(float);  // 120,552 B
    if (!smem_set) {
        cudaFuncSetAttribute(se3_frame_kernel,
                             cudaFuncAttributeMaxDynamicSharedMemorySize, smem_bytes);
        smem_set = 1;
    }

    se3_frame_kernel<<<T_, THREADS, smem_bytes>>>(can, def, nbr, mask, out);
}

// round 17
// speedup vs baseline: 1.1582x; 1.1582x over previous
#include <cuda_runtime.h>
#include <cstdint>

#define T_ 128
#define V_ 5023
#define K_ 16
#define NTV (T_ * V_)
#define THREADS 1024

extern __shared__ float s_rec[];  // [6 * V_] : {can.xyz, def.xyz} per vertex

// 4D cross product: vector orthogonal to rows rA, rB, rC (null vector of B
// when rows are 3 independent rows of singular symmetric B).
__device__ __forceinline__ void cross4(
    const float* rA, const float* rB, const float* rC,
    float& n0, float& n1, float& n2, float& n3) {
    float m01 = rB[0] * rC[1] - rB[1] * rC[0];
    float m02 = rB[0] * rC[2] - rB[2] * rC[0];
    float m03 = rB[0] * rC[3] - rB[3] * rC[0];
    float m12 = rB[1] * rC[2] - rB[2] * rC[1];
    float m13 = rB[1] * rC[3] - rB[3] * rC[1];
    float m23 = rB[2] * rC[3] - rB[3] * rC[2];
    n0 =  (rA[1] * m23 - rA[2] * m13 + rA[3] * m12);
    n1 = -(rA[0] * m23 - rA[2] * m03 + rA[3] * m02);
    n2 =  (rA[0] * m13 - rA[1] * m03 + rA[3] * m01);
    n3 = -(rA[0] * m12 - rA[1] * m02 + rA[2] * m01);
}

__global__ void __launch_bounds__(THREADS)
se3_frame_kernel(const float* __restrict__ can, const float* __restrict__ def,
                 const int* __restrict__ nbr, const void* __restrict__ maskp,
                 float* __restrict__ out) {
    const int t = blockIdx.x;
    const int tid = threadIdx.x;
    const float* canT = can + (size_t)t * (V_ * 3);
    const float* defT = def + (size_t)t * (V_ * 3);

    __shared__ int s_mode;  // 0 = uint8 bool, 1 = int32, 2 = float32

    // ---- inline mask dtype detection (warp 0, first 32 words) ----
    if (tid < 32) {
        unsigned int x = ((const unsigned int*)maskp)[tid];
        bool weird = (x != 0u) && (x != 1u) && (x != 0x3F800000u);
        bool isf32 = (x == 0x3F800000u);
        unsigned bp = __ballot_sync(0xffffffffu, weird);
        unsigned fp = __ballot_sync(0xffffffffu, isf32);
        if (tid == 0) s_mode = bp ? 0 : (fp ? 2 : 1);
    }

    // ---- stage this frame's positions into smem as packed 24B records ----
    for (int v = tid; v < V_; v += THREADS) {
        int b = 3 * v;
        float* r = s_rec + 6 * v;
        r[0] = canT[b]; r[1] = canT[b + 1]; r[2] = canT[b + 2];
        r[3] = defT[b]; r[4] = defT[b + 1]; r[5] = defT[b + 2];
    }
    __syncthreads();

    const int mode = s_mode;
    float* outt = out + (size_t)NTV * 4;

    for (int v = tid; v < V_; v += THREADS) {
        // ---- active-neighbor bitmask (dtype-robust; uniform branch) ----
        unsigned int amask = 0;
        if (mode == 0) {
            uint4 mw = *(const uint4*)((const unsigned char*)maskp + (size_t)v * K_);
            unsigned int ws[4] = {mw.x, mw.y, mw.z, mw.w};
#pragma unroll
            for (int i = 0; i < K_; i++)
                if ((ws[i >> 2] >> ((i & 3) * 8)) & 0xFF) amask |= (1u << i);
        } else if (mode == 1) {
            const int4* mi = (const int4*)((const int*)maskp + (size_t)v * K_);
#pragma unroll
            for (int c = 0; c < 4; c++) {
                int4 x = mi[c];
                if (x.x) amask |= 1u << (c * 4 + 0);
                if (x.y) amask |= 1u << (c * 4 + 1);
                if (x.z) amask |= 1u << (c * 4 + 2);
                if (x.w) amask |= 1u << (c * 4 + 3);
            }
        } else {
            const float4* mf = (const float4*)((const float*)maskp + (size_t)v * K_);
#pragma unroll
            for (int c = 0; c < 4; c++) {
                float4 x = mf[c];
                if (x.x != 0.0f) amask |= 1u << (c * 4 + 0);
                if (x.y != 0.0f) amask |= 1u << (c * 4 + 1);
                if (x.z != 0.0f) amask |= 1u << (c * 4 + 2);
                if (x.w != 0.0f) amask |= 1u << (c * 4 + 3);
            }
        }

        // ---- neighbor indices ----
        int nb[K_];
        const int4* ni = (const int4*)(nbr + (size_t)v * K_);
#pragma unroll
        for (int c = 0; c < 4; c++) {
            int4 x = ni[c];
            nb[c * 4 + 0] = x.x; nb[c * 4 + 1] = x.y;
            nb[c * 4 + 2] = x.z; nb[c * 4 + 3] = x.w;
        }

        const float* rv = s_rec + 6 * v;
        float cx = rv[0], cy = rv[1], cz = rv[2];
        float dx = rv[3], dy = rv[4], dz = rv[5];

        // ---- masked gather sums over ACTIVE neighbors only (R6 structure) ----
        float G1x = 0, G1y = 0, G1z = 0;
        float G2x = 0, G2y = 0, G2z = 0;
        float G300 = 0, G301 = 0, G302 = 0;
        float G310 = 0, G311 = 0, G312 = 0;
        float G320 = 0, G321 = 0, G322 = 0;
#pragma unroll
        for (int k = 0; k < K_; k += 2) {
            bool a0 = (amask >> k) & 1u;
            bool a1_ = (amask >> (k + 1)) & 1u;
            float2 r0a, r1a, r2a, r0b, r1b, r2b;
            if (a0) {
                const float2* rj = (const float2*)(s_rec + 6 * nb[k]);
                r0a = rj[0]; r1a = rj[1]; r2a = rj[2];
            }
            if (a1_) {
                const float2* rj = (const float2*)(s_rec + 6 * nb[k + 1]);
                r0b = rj[0]; r1b = rj[1]; r2b = rj[2];
            }
            if (a0) {
                float px = r0a.x, py = r0a.y, pz = r1a.x;
                float qx = r1a.y, qy = r2a.x, qz = r2a.y;
                G1x += px; G1y += py; G1z += pz;
                G2x += qx; G2y += qy; G2z += qz;
                G300 = fmaf(qx, px, G300); G301 = fmaf(qx, py, G301); G302 = fmaf(qx, pz, G302);
                G310 = fmaf(qy, px, G310); G311 = fmaf(qy, py, G311); G312 = fmaf(qy, pz, G312);
                G320 = fmaf(qz, px, G320); G321 = fmaf(qz, py, G321); G322 = fmaf(qz, pz, G322);
            }
            if (a1_) {
                float px = r0b.x, py = r0b.y, pz = r1b.x;
                float qx = r1b.y, qy = r2b.x, qz = r2b.y;
                G1x += px; G1y += py; G1z += pz;
                G2x += qx; G2y += qy; G2z += qz;
                G300 = fmaf(qx, px, G300); G301 = fmaf(qx, py, G301); G302 = fmaf(qx, pz, G302);
                G310 = fmaf(qy, px, G310); G311 = fmaf(qy, py, G311); G312 = fmaf(qy, pz, G312);
                G320 = fmaf(qz, px, G320); G321 = fmaf(qz, py, G321); G322 = fmaf(qz, pz, G322);
            }
        }

        // A[i][j] = G3[i][j] - G2_i*c_j - d_i*(G1_j - 16*c_j)
        float Hx = fmaf(-16.0f, cx, G1x);
        float Hy = fmaf(-16.0f, cy, G1y);
        float Hz = fmaf(-16.0f, cz, G1z);
        float A00 = G300 - G2x * cx - dx * Hx;
        float A01 = G301 - G2x * cy - dx * Hy;
        float A02 = G302 - G2x * cz - dx * Hz;
        float A10 = G310 - G2y * cx - dy * Hx;
        float A11 = G311 - G2y * cy - dy * Hy;
        float A12 = G312 - G2y * cz - dy * Hz;
        float A20 = G320 - G2z * cx - dz * Hx;
        float A21 = G321 - G2z * cy - dz * Hy;
        float A22 = G322 - G2z * cz - dz * Hz;

        int idx = t * V_ + v;
        outt[idx * 3 + 0] = dx - cx;
        outt[idx * 3 + 1] = dy - cy;
        outt[idx * 3 + 2] = dz - cz;

        // ---- characteristic quartic via invariants of M = A^T A ----
        // c2 = -2 trM ; c1 = -8 detA ; c0 = 2 tr(M^2) - (trM)^2
        float M00v = A00 * A00 + A10 * A10 + A20 * A20;
        float M11v = A01 * A01 + A11 * A11 + A21 * A21;
        float M22v = A02 * A02 + A12 * A12 + A22 * A22;
        float M01v = A00 * A01 + A10 * A11 + A20 * A21;
        float M02v = A00 * A02 + A10 * A12 + A20 * A22;
        float M12v = A01 * A02 + A11 * A12 + A21 * A22;
        float trM = M00v + M11v + M22v;
        float trM2 = M00v * M00v + M11v * M11v + M22v * M22v +
                     2.0f * (M01v * M01v + M02v * M02v + M12v * M12v);
        float c2 = -2.0f * trM;
        float detA = A00 * (A11 * A22 - A12 * A21)
                   - A01 * (A10 * A22 - A12 * A20)
                   + A02 * (A10 * A21 - A11 * A20);
        float c1 = -8.0f * detA;
        float c0 = 2.0f * trM2 - trM * trM;

        // ---- Newton from tight upper bound ----
        // e2 = sum sigma_i^2 sigma_j^2 = ((trM)^2 - trM2)/2 ;
        // lam0 = sqrt(trM + 2*sqrt(3*e2)) >= sigma1+sigma2+sigma3
        float e2 = 0.5f * (trM * trM - trM2);
        e2 = fmaxf(e2, 0.0f);
        float lam = sqrtf(trM + 2.0f * sqrtf(3.0f * e2));
#pragma unroll
        for (int it = 0; it < 8; it++) {
            float lam2 = lam * lam;
            float f = (lam2 + c2) * lam2 + fmaf(c1, lam, c0);
            float fp = fmaf(4.0f * lam2 + 2.0f * c2, lam, c1);
            lam -= __fdividef(f, fp);
        }

        // ---- Davenport K matrix, B = K - lam I ----
        float b00 = (A00 + A11 + A22) - lam;
        float b11 = (A00 - A11 - A22) - lam;
        float b22 = (-A00 + A11 - A22) - lam;
        float b33 = (-A00 - A11 + A22) - lam;
        float k01 = A21 - A12;
        float k02 = A02 - A20;
        float k03 = A10 - A01;
        float k12 = A01 + A10;
        float k13 = A02 + A20;
        float k23 = A12 + A21;

        float r0[4] = {b00, k01, k02, k03};
        float r1[4] = {k01, b11, k12, k13};
        float r2[4] = {k02, k12, b22, k23};
        float r3[4] = {k03, k13, k23, b33};

        // null vector of B via 4D cross product of rows 1,2,3
        float qw, qx, qy, qz;
        cross4(r1, r2, r3, qw, qx, qy, qz);

        float nq = fmaf(qw, qw, fmaf(qx, qx, fmaf(qy, qy, qz * qz)));
        // scale reference: adj-column magnitude ~ lam^6; tiny => qw ~ 0 (near-180 rot)
        float lam2s = lam * lam;
        float thr = 1e-10f * lam2s * lam2s * lam2s;
        if (nq < thr) {
            cross4(r0, r2, r3, qw, qx, qy, qz);
            float nq2 = fmaf(qw, qw, fmaf(qx, qx, fmaf(qy, qy, qz * qz)));
            if (nq2 < thr) cross4(r0, r1, r3, qw, qx, qy, qz);
        }

        // sign convention: component with largest |value| (w,x,y,z, first on ties) positive
        float aw = fabsf(qw), ax = fabsf(qx), ay = fabsf(qy), az = fabsf(qz);
        float besta = aw, piv = qw;
        if (ax > besta) { besta = ax; piv = qx; }
        if (ay > besta) { besta = ay; piv = qy; }
        if (az > besta) { besta = az; piv = qz; }
        float invn = rsqrtf(fmaf(qw, qw, fmaf(qx, qx, fmaf(qy, qy, qz * qz))));
        if (piv < 0.0f) invn = -invn;

        ((float4*)out)[idx] = make_float4(qw * invn, qx * invn, qy * invn, qz * invn);
    }
}

extern "C" void kernel_launch(void* const* d_in, const int* in_sizes, int n_in,
                              void* d_out, int out_size) {
    const float* can = (const float*)d_in[0];
    const float* def = (const float*)d_in[1];
    const int* nbr = (const int*)d_in[2];
    const void* mask = d_in[3];
    float* out = (float*)d_out;

    static int smem_set = 0;
    const int smem_bytes = 6 * V_ * (int)sizeof(float);  // 120,552 B
    if (!smem_set) {
        cudaFuncSetAttribute(se3_frame_kernel,
                             cudaFuncAttributeMaxDynamicSharedMemorySize, smem_bytes);
        smem_set = 1;
    }

    se3_frame_kernel<<<T_, THREADS, smem_bytes>>>(can, def, nbr, mask, out);
}